// round 1
// baseline (speedup 1.0000x reference)
#include <cuda_runtime.h>

// context_window: out[b, f*11 + c, t] = x[b, f, t + c - 5], zero-padded in t.
// x: (32, 80, 3000) fp32 -> out: (32, 880, 3000) fp32.
// Hardcoded per the reference setup: B=32, F=80, T=3000, L=R=5, C=11.

#define T_DIM   3000
#define C_LEN   11
#define ROWS    (32 * 80)     // B*F = 2560
#define T4      (T_DIM / 4)   // 750 float4 chunks per row

__global__ __launch_bounds__(256) void context_window_kernel(
    const float* __restrict__ x, float* __restrict__ out)
{
    int t4 = blockIdx.x * blockDim.x + threadIdx.x;
    if (t4 >= T4) return;
    int row = blockIdx.y;                 // b*80 + f
    int t = t4 * 4;

    const float* __restrict__ xr = x + row * T_DIM;

    // Register window covering x[t-8 .. t+11] (indices k -> t-8+k).
    // Output (c, t+j) = x[t + j + c - 5] = w[j + c + 3]; used range w[3..16].
    float w[20];

    if (t4 >= 2 && t4 <= T4 - 3) {
        // Fast path: 5 aligned float4 loads, fully in-range.
        const float4* __restrict__ p = reinterpret_cast<const float4*>(xr + t - 8);
        #pragma unroll
        for (int i = 0; i < 5; i++) {
            float4 v = p[i];
            w[4*i + 0] = v.x; w[4*i + 1] = v.y;
            w[4*i + 2] = v.z; w[4*i + 3] = v.w;
        }
    } else {
        // Edge path (t4 in {0,1,748,749}): scalar bounds-checked loads.
        #pragma unroll
        for (int k = 0; k < 20; k++) {
            int idx = t - 8 + k;
            w[k] = (idx >= 0 && idx < T_DIM) ? xr[idx] : 0.0f;
        }
    }

    // 11 coalesced, aligned float4 stores — one per context shift.
    float* __restrict__ orow = out + (row * C_LEN) * T_DIM + t;
    #pragma unroll
    for (int c = 0; c < C_LEN; c++) {
        float4 v = make_float4(w[c + 3], w[c + 4], w[c + 5], w[c + 6]);
        *reinterpret_cast<float4*>(orow + c * T_DIM) = v;
    }
}

extern "C" void kernel_launch(void* const* d_in, const int* in_sizes, int n_in,
                              void* d_out, int out_size)
{
    const float* x = (const float*)d_in[0];
    float* out = (float*)d_out;

    dim3 block(256);
    dim3 grid((T4 + 255) / 256, ROWS);   // (3, 2560)
    context_window_kernel<<<grid, block>>>(x, out);
}